// round 8
// baseline (speedup 1.0000x reference)
#include <cuda_runtime.h>
#include <math.h>
#include <stdint.h>

// ---------------- problem constants (fixed by the dataset) ----------------
#define N_M   8192
#define N_D   6144
#define NTOT  14336            // N_M + N_D
#define E_MM  131072
#define E_DD  98304
#define E_G   229376
#define EG_TOT (E_G + NTOT)    // real edges + self loops = 243712
#define HID   128
#define TPB   256

// ---------------- scratch (static device globals; no runtime alloc) -------
__device__ float g_ew_m[E_MM];
__device__ float g_ew_d[E_DD];
__device__ float g_deg_m[N_M];
__device__ float g_deg_d[N_D];
__device__ int   g_cnt_m[N_M],  g_row_m[N_M + 1],  g_cur_m[N_M];
__device__ int   g_src_m[E_MM];  __device__ float g_w_m[E_MM];
__device__ int   g_cnt_d[N_D],  g_row_d[N_D + 1],  g_cur_d[N_D];
__device__ int   g_src_d[E_DD];  __device__ float g_w_d[E_DD];
__device__ int   g_cnt_g[NTOT], g_row_g[NTOT + 1], g_cur_g[NTOT];
__device__ int   g_src_g[EG_TOT];
__device__ float g_bufA[(size_t)NTOT * 256];
__device__ float g_bufB[(size_t)NTOT * 256];
__device__ float g_tmp [(size_t)NTOT * 128];
__device__ float g_xjk [(size_t)NTOT * 224];

__device__ __forceinline__ float4 ld4(const float* p) { return *(const float4*)p; }

// tf32 conversion (round-to-nearest) — bit pattern in a u32
__device__ __forceinline__ uint32_t f2tf(float x) {
    uint32_t r;
    asm("cvt.rna.tf32.f32 %0, %1;" : "=r"(r) : "f"(x));
    return r;
}

// one m16n8k8 tf32 mma, D += A*B (D==C in-place)
__device__ __forceinline__ void mma8(float* d, const uint32_t* a, uint32_t b0, uint32_t b1) {
    asm("mma.sync.aligned.m16n8k8.row.col.f32.tf32.tf32.f32 "
        "{%0,%1,%2,%3}, {%4,%5,%6,%7}, {%8,%9}, {%0,%1,%2,%3};"
        : "+f"(d[0]), "+f"(d[1]), "+f"(d[2]), "+f"(d[3])
        : "r"(a[0]), "r"(a[1]), "r"(a[2]), "r"(a[3]), "r"(b0), "r"(b1));
}

// ---------------- init ----------------
__global__ void k_init() {
    int i = blockIdx.x * blockDim.x + threadIdx.x;
    if (i < N_M)  { g_deg_m[i] = 1.0f; g_cnt_m[i] = 0; }   // self-loop weight 1
    if (i < N_D)  { g_deg_d[i] = 1.0f; g_cnt_d[i] = 0; }
    if (i < NTOT) { g_cnt_g[i] = 1; }                       // self loop pre-counted
}

// ---------------- combined edge prep (both GCN graphs + GAT count) --------
__global__ void k_prep_all(const int* __restrict__ e_mm, const float* __restrict__ msM,
                           const int* __restrict__ e_dd, const float* __restrict__ dsM,
                           const int* __restrict__ e_g) {
    int i = blockIdx.x * blockDim.x + threadIdx.x;
    if (i < E_MM) {
        int s = e_mm[i], d = e_mm[E_MM + i];
        float w = msM[(size_t)s * N_M + d];
        g_ew_m[i] = w;
        atomicAdd(&g_deg_m[d], w);
        atomicAdd(&g_cnt_m[d], 1);
    } else if (i < E_MM + E_DD) {
        int f = i - E_MM;
        int s = e_dd[f], d = e_dd[E_DD + f];
        float w = dsM[(size_t)s * N_D + d];
        g_ew_d[f] = w;
        atomicAdd(&g_deg_d[d], w);
        atomicAdd(&g_cnt_d[d], 1);
    } else if (i < E_MM + E_DD + E_G) {
        int f = i - E_MM - E_DD;
        atomicAdd(&g_cnt_g[e_g[E_G + f]], 1);
    }
}

// ---------------- 3 scans in one launch (blockIdx picks the graph) --------
__global__ void k_scan3() {
    __shared__ int sh[1024];
    const int* cnt; int* row; int* cur; int n;
    if (blockIdx.x == 0)      { cnt = g_cnt_m; row = g_row_m; cur = g_cur_m; n = N_M; }
    else if (blockIdx.x == 1) { cnt = g_cnt_d; row = g_row_d; cur = g_cur_d; n = N_D; }
    else                      { cnt = g_cnt_g; row = g_row_g; cur = g_cur_g; n = NTOT; }
    int t = threadIdx.x;
    int chunk = (n + 1023) / 1024;
    int lo = t * chunk, hi = min(lo + chunk, n);
    int sum = 0;
    for (int i = lo; i < hi; i++) sum += cnt[i];
    sh[t] = sum;
    __syncthreads();
    for (int off = 1; off < 1024; off <<= 1) {
        int v = 0;
        if (t >= off) v = sh[t - off];
        __syncthreads();
        if (t >= off) sh[t] += v;
        __syncthreads();
    }
    int run = (t == 0) ? 0 : sh[t - 1];
    for (int i = lo; i < hi; i++) { row[i] = run; cur[i] = run; run += cnt[i]; }
    if (t == 1023) row[n] = sh[1023];
}

// ---------------- combined CSR fill; GCN norm computed inline -------------
__global__ void k_fill_all(const int* __restrict__ e_mm, const int* __restrict__ e_dd,
                           const int* __restrict__ e_g) {
    int i = blockIdx.x * blockDim.x + threadIdx.x;
    if (i < E_MM) {
        int s = e_mm[i], d = e_mm[E_MM + i];
        int p = atomicAdd(&g_cur_m[d], 1);
        g_src_m[p] = s;
        g_w_m[p] = rsqrtf(g_deg_m[s]) * g_ew_m[i] * rsqrtf(g_deg_m[d]);
    } else if (i < E_MM + E_DD) {
        int f = i - E_MM;
        int s = e_dd[f], d = e_dd[E_DD + f];
        int p = atomicAdd(&g_cur_d[d], 1);
        g_src_d[p] = s;
        g_w_d[p] = rsqrtf(g_deg_d[s]) * g_ew_d[f] * rsqrtf(g_deg_d[d]);
    } else if (i < E_MM + E_DD + E_G) {
        int f = i - E_MM - E_DD;
        int d = e_g[E_G + f];
        int p = atomicAdd(&g_cur_g[d], 1);
        g_src_g[p] = e_g[f];
    } else if (i < E_MM + E_DD + E_G + NTOT) {
        int f = i - E_MM - E_DD - E_G;     // self loop
        int p = atomicAdd(&g_cur_g[f], 1);
        g_src_g[p] = f;
    }
}

// ---------------- tf32x3 tensor-core GEMM: 128x128x16 tiles ----------------
// 8 warps (4x2), warp tile m32 x n64, mma.m16n8k8.tf32, 3-pass compensation.
// Register double-buffering: next tile's LDGs issue BEFORE the mma section,
// overlapping global-load latency with tensor work.
struct GTask { const float* A; const float* W1; const float* W2; float* C1; float* C2; int M; };

__global__ __launch_bounds__(256) void k_gemm(
        GTask ta, GTask tb,
        int lda, int Nsplit, int ldw, const float* bias, int ldc, int K) {
    __shared__ uint32_t As_h[16][132], As_l[16][132];   // [k][m], pad 4
    __shared__ uint32_t Bs_h[16][132], Bs_l[16][132];   // [k][n], pad 4
    GTask t = (blockIdx.z == 0) ? ta : tb;
    int row0 = blockIdx.y * 128;
    if (row0 >= t.M) return;
    int col0 = blockIdx.x * 128;
    const float* Wb; float* Cb;
    if (col0 < Nsplit) { Wb = t.W1 + col0;            Cb = t.C1 + col0; }
    else               { Wb = t.W2 + (col0 - Nsplit); Cb = t.C2 + (col0 - Nsplit); }

    int tid = threadIdx.x;
    int lane = tid & 31, wid = tid >> 5;
    int warp_m = wid & 3, warp_n = wid >> 2;   // 4 x 2 warp grid
    int g = lane >> 2, tg = lane & 3;
    int mbase = warp_m * 32, nbase0 = warp_n * 64;

    // per-thread load geometry (constant across k-iterations)
    int ar0 = tid >> 2,          ac4 = tid & 3;        // A: rows ar0, ar0+64
    int ar1 = (tid + 256) >> 2;
    int br0 = tid >> 5,          bc4 = tid & 31;       // B: k-rows br0, br0+8
    const float* pA0 = t.A + (size_t)(row0 + ar0) * lda + ac4 * 4;
    const float* pA1 = t.A + (size_t)(row0 + ar1) * lda + ac4 * 4;
    const float* pB0 = Wb + (size_t)br0 * ldw + bc4 * 4;
    const float* pB1 = Wb + (size_t)(br0 + 8) * ldw + bc4 * 4;

    float acc[2][8][4];
    #pragma unroll
    for (int mi = 0; mi < 2; mi++)
        #pragma unroll
        for (int ni = 0; ni < 8; ni++)
            #pragma unroll
            for (int q = 0; q < 4; q++) acc[mi][ni][q] = 0.f;

    // preload tile 0 into registers
    float4 ra0 = ld4(pA0), ra1 = ld4(pA1);
    float4 rb0 = ld4(pB0), rb1 = ld4(pB1);

    for (int k0 = 0; k0 < K; k0 += 16) {
        // convert + store current tile (regs -> smem)
        {
            float ea[4] = {ra0.x, ra0.y, ra0.z, ra0.w};
            float eb[4] = {ra1.x, ra1.y, ra1.z, ra1.w};
            #pragma unroll
            for (int j = 0; j < 4; j++) {
                uint32_t h0 = f2tf(ea[j]);
                As_h[ac4 * 4 + j][ar0] = h0;
                As_l[ac4 * 4 + j][ar0] = f2tf(ea[j] - __uint_as_float(h0));
                uint32_t h1 = f2tf(eb[j]);
                As_h[ac4 * 4 + j][ar1] = h1;
                As_l[ac4 * 4 + j][ar1] = f2tf(eb[j] - __uint_as_float(h1));
            }
            uint4 hv, lv;
            hv.x = f2tf(rb0.x); lv.x = f2tf(rb0.x - __uint_as_float(hv.x));
            hv.y = f2tf(rb0.y); lv.y = f2tf(rb0.y - __uint_as_float(hv.y));
            hv.z = f2tf(rb0.z); lv.z = f2tf(rb0.z - __uint_as_float(hv.z));
            hv.w = f2tf(rb0.w); lv.w = f2tf(rb0.w - __uint_as_float(hv.w));
            *(uint4*)&Bs_h[br0][bc4 * 4] = hv;
            *(uint4*)&Bs_l[br0][bc4 * 4] = lv;
            hv.x = f2tf(rb1.x); lv.x = f2tf(rb1.x - __uint_as_float(hv.x));
            hv.y = f2tf(rb1.y); lv.y = f2tf(rb1.y - __uint_as_float(hv.y));
            hv.z = f2tf(rb1.z); lv.z = f2tf(rb1.z - __uint_as_float(hv.z));
            hv.w = f2tf(rb1.w); lv.w = f2tf(rb1.w - __uint_as_float(hv.w));
            *(uint4*)&Bs_h[br0 + 8][bc4 * 4] = hv;
            *(uint4*)&Bs_l[br0 + 8][bc4 * 4] = lv;
        }
        __syncthreads();

        // prefetch next tile (overlaps with mma below)
        if (k0 + 16 < K) {
            ra0 = ld4(pA0 + k0 + 16);
            ra1 = ld4(pA1 + k0 + 16);
            rb0 = ld4(pB0 + (size_t)(k0 + 16) * ldw);
            rb1 = ld4(pB1 + (size_t)(k0 + 16) * ldw);
        }

        #pragma unroll
        for (int ks = 0; ks < 16; ks += 8) {
            uint32_t ah[2][4], al[2][4];
            #pragma unroll
            for (int mi = 0; mi < 2; mi++) {
                int m0 = mbase + mi * 16;
                ah[mi][0] = As_h[ks + tg][m0 + g];
                ah[mi][1] = As_h[ks + tg][m0 + g + 8];
                ah[mi][2] = As_h[ks + tg + 4][m0 + g];
                ah[mi][3] = As_h[ks + tg + 4][m0 + g + 8];
                al[mi][0] = As_l[ks + tg][m0 + g];
                al[mi][1] = As_l[ks + tg][m0 + g + 8];
                al[mi][2] = As_l[ks + tg + 4][m0 + g];
                al[mi][3] = As_l[ks + tg + 4][m0 + g + 8];
            }
            #pragma unroll
            for (int ni = 0; ni < 8; ni++) {
                int n0 = nbase0 + ni * 8;
                uint32_t bh0 = Bs_h[ks + tg][n0 + g];
                uint32_t bh1 = Bs_h[ks + tg + 4][n0 + g];
                uint32_t bl0 = Bs_l[ks + tg][n0 + g];
                uint32_t bl1 = Bs_l[ks + tg + 4][n0 + g];
                #pragma unroll
                for (int mi = 0; mi < 2; mi++) {
                    mma8(acc[mi][ni], ah[mi], bl0, bl1);   // hi * lo
                    mma8(acc[mi][ni], al[mi], bh0, bh1);   // lo * hi
                    mma8(acc[mi][ni], ah[mi], bh0, bh1);   // hi * hi
                }
            }
        }
        __syncthreads();
    }

    // epilogue: thread owns rows {g, g+8} of each m16 tile, cols {2tg, 2tg+1}
    #pragma unroll
    for (int mi = 0; mi < 2; mi++) {
        int r0 = row0 + mbase + mi * 16 + g;
        #pragma unroll
        for (int ni = 0; ni < 8; ni++) {
            int lc = nbase0 + ni * 8 + tg * 2;
            float b0 = 0.f, b1 = 0.f;
            if (bias) { b0 = bias[col0 + lc]; b1 = bias[col0 + lc + 1]; }
            float* p0 = Cb + (size_t)r0 * ldc + lc;
            float* p1 = p0 + (size_t)8 * ldc;
            *(float2*)p0 = make_float2(acc[mi][ni][0] + b0, acc[mi][ni][1] + b1);
            *(float2*)p1 = make_float2(acc[mi][ni][2] + b0, acc[mi][ni][3] + b1);
        }
    }
}

// ---------------- GCN aggregate, both graphs in one launch ----------------
__global__ void k_gcn_agg2(const float* __restrict__ h,
                           const float* __restrict__ bias_m, const float* __restrict__ bias_d,
                           float* __restrict__ out_m, float* __restrict__ out_d,
                           int ldm, int ldd) {
    int w = (blockIdx.x * blockDim.x + threadIdx.x) >> 5;
    int lane = threadIdx.x & 31;
    if (w >= NTOT) return;
    const int* row; const int* src; const float* wcs; const float* bias;
    const float* hb; const float* deg; float* po; int node;
    if (w < N_M) {
        node = w; row = g_row_m; src = g_src_m; wcs = g_w_m; bias = bias_m;
        hb = h; deg = g_deg_m;
        po = out_m + (size_t)w * ldm + lane * 4;
    } else {
        node = w - N_M; row = g_row_d; src = g_src_d; wcs = g_w_d; bias = bias_d;
        hb = h + (size_t)N_M * HID; deg = g_deg_d;
        po = out_d + (size_t)(w - N_M) * ldd + lane * 4;
    }
    int rs = row[node], re = row[node + 1];
    float4 acc = make_float4(0.f, 0.f, 0.f, 0.f);
    for (int j = rs; j < re; j++) {
        int s = src[j];
        float nm = wcs[j];
        float4 v = ld4(hb + (size_t)s * HID + lane * 4);
        acc.x += nm * v.x; acc.y += nm * v.y; acc.z += nm * v.z; acc.w += nm * v.w;
    }
    float di = rsqrtf(deg[node]);
    float sw = di * di;
    float4 v = ld4(hb + (size_t)node * HID + lane * 4);
    acc.x += sw * v.x; acc.y += sw * v.y; acc.z += sw * v.z; acc.w += sw * v.w;
    float4 b = ld4(bias + lane * 4);
    acc.x = fmaxf(acc.x + b.x, 0.f); acc.y = fmaxf(acc.y + b.y, 0.f);
    acc.z = fmaxf(acc.z + b.z, 0.f); acc.w = fmaxf(acc.w + b.w, 0.f);
    *(float4*)po = acc;
}

// ---------------- Fused GATv2 (warp per dst node, online softmax) ---------
template <int HC>
__global__ void k_gat_fused(const float* __restrict__ xl, const float* __restrict__ xr,
                            const float* __restrict__ att,
                            const float* __restrict__ bias,
                            float* __restrict__ out, int ldout, int elu) {
    const int CH = HC / 32;
    int i = (blockIdx.x * blockDim.x + threadIdx.x) >> 5;
    int lane = threadIdx.x & 31;
    if (i >= NTOT) return;
    int rs = g_row_g[i], re = g_row_g[i + 1];

    float attv[CH], xrv[CH];
    #pragma unroll
    for (int k = 0; k < CH; k += 4) {
        float4 a = ld4(att + lane * CH + k);
        attv[k] = a.x; attv[k + 1] = a.y; attv[k + 2] = a.z; attv[k + 3] = a.w;
        float4 r = ld4(xr + (size_t)i * HC + lane * CH + k);
        xrv[k] = r.x; xrv[k + 1] = r.y; xrv[k + 2] = r.z; xrv[k + 3] = r.w;
    }

    float m = -1e30f, den = 0.f;
    float num[CH];
    #pragma unroll
    for (int k = 0; k < CH; k++) num[k] = 0.f;

    for (int j = rs; j < re; j++) {
        int s = g_src_g[j];
        float xlv[CH];
        float p = 0.f;
        #pragma unroll
        for (int k = 0; k < CH; k += 4) {
            float4 v = ld4(xl + (size_t)s * HC + lane * CH + k);
            xlv[k] = v.x; xlv[k + 1] = v.y; xlv[k + 2] = v.z; xlv[k + 3] = v.w;
        }
        #pragma unroll
        for (int k = 0; k < CH; k++) {
            float t = xlv[k] + xrv[k];
            t = t > 0.f ? t : 0.2f * t;
            p += t * attv[k];
        }
        p += __shfl_xor_sync(0xffffffffu, p, 1);
        p += __shfl_xor_sync(0xffffffffu, p, 2);
        p += __shfl_xor_sync(0xffffffffu, p, 4);
        float mn = fmaxf(m, p);
        float c  = expf(m - mn);      // first iter: exp(-huge) = 0
        float ex = expf(p - mn);
        den = den * c + ex;
        #pragma unroll
        for (int k = 0; k < CH; k++) num[k] = num[k] * c + ex * xlv[k];
        m = mn;
    }

    float inv = 0.25f / den;   // includes 1/H head-mean
    #pragma unroll
    for (int k = 0; k < CH; k++) {
        float v = num[k] * inv;
        v += __shfl_xor_sync(0xffffffffu, v, 8);
        v += __shfl_xor_sync(0xffffffffu, v, 16);
        num[k] = v;
    }
    if (lane < 8) {
        float o[CH];
        #pragma unroll
        for (int k = 0; k < CH; k++) {
            float v = num[k] + bias[lane * CH + k];
            if (elu) v = v > 0.f ? v : expm1f(v);
            o[k] = v;
        }
        float* po = out + (size_t)i * ldout + lane * CH;
        #pragma unroll
        for (int k = 0; k < CH; k += 4)
            *(float4*)(po + k) = make_float4(o[k], o[k + 1], o[k + 2], o[k + 3]);
    }
}

// ---------------- host orchestration ----------------
extern "C" void kernel_launch(void* const* d_in, const int* in_sizes, int n_in,
                              void* d_out, int out_size) {
    const float* mm_f = (const float*)d_in[0];
    const float* d_s  = (const float*)d_in[1];
    const float* msM  = (const float*)d_in[2];
    const float* dsM  = (const float*)d_in[3];
    const int*   e_mm = (const int*)d_in[4];
    const int*   e_dd = (const int*)d_in[5];
    const int*   e_g  = (const int*)d_in[6];
    const float* W_m1 = (const float*)d_in[7];  const float* b_m1 = (const float*)d_in[8];
    const float* W_m2 = (const float*)d_in[9];  const float* b_m2 = (const float*)d_in[10];
    const float* W_d1 = (const float*)d_in[11]; const float* b_d1 = (const float*)d_in[12];
    const float* W_d2 = (const float*)d_in[13]; const float* b_d2 = (const float*)d_in[14];
    const float* Wl1  = (const float*)d_in[15]; const float* Wr1  = (const float*)d_in[16];
    const float* att1 = (const float*)d_in[17]; const float* bias1 = (const float*)d_in[18];
    const float* Wl2  = (const float*)d_in[19]; const float* Wr2  = (const float*)d_in[20];
    const float* att2 = (const float*)d_in[21]; const float* bias2 = (const float*)d_in[22];
    const float* Wjk  = (const float*)d_in[23]; const float* bjk  = (const float*)d_in[24];
    float* out = (float*)d_out;

    float *p_A, *p_B, *p_tmp, *p_xjk;
    cudaGetSymbolAddress((void**)&p_A,   g_bufA);
    cudaGetSymbolAddress((void**)&p_B,   g_bufB);
    cudaGetSymbolAddress((void**)&p_tmp, g_tmp);
    cudaGetSymbolAddress((void**)&p_xjk, g_xjk);

    const int GB = TPB;
    auto blk = [](int n) { return (n + TPB - 1) / TPB; };
    auto wblk = [](int nwarps) { return (nwarps * 32 + TPB - 1) / TPB; };

    // ---- prep + GCN layer1 GEMM (gemm1 moved to launch #4 so the ncu
    //      fixed-index capture profiles the GEMM next round; gemm1 only
    //      depends on kernel inputs, so the reorder is legal) ----
    k_init<<<blk(NTOT), GB>>>();
    k_prep_all<<<blk(E_MM + E_DD + E_G), GB>>>(e_mm, msM, e_dd, dsM, e_g);
    k_scan3<<<3, 1024>>>();
    {
        GTask ta = { mm_f, W_m1, W_m1, p_A,                      p_A,                      N_M };
        GTask tb = { d_s,  W_d1, W_d1, p_A + (size_t)N_M * HID,  p_A + (size_t)N_M * HID,  N_D };
        k_gemm<<<dim3(1, N_M / 128, 2), 256>>>(ta, tb, HID, 128, HID, nullptr, HID, HID);
    }
    k_fill_all<<<blk(E_MM + E_DD + E_G + NTOT), GB>>>(e_mm, e_dd, e_g);

    // ---- GCN layer 1 aggregate ----
    k_gcn_agg2<<<wblk(NTOT), GB>>>(p_A, b_m1, b_d1, p_tmp, p_tmp + (size_t)N_M * HID, HID, HID);

    // ---- GCN layer 2 ----
    {
        GTask ta = { p_tmp,                      W_m2, W_m2, p_A,                     p_A,                     N_M };
        GTask tb = { p_tmp + (size_t)N_M * HID,  W_d2, W_d2, p_A + (size_t)N_M * HID, p_A + (size_t)N_M * HID, N_D };
        k_gemm<<<dim3(1, N_M / 128, 2), 256>>>(ta, tb, HID, 128, HID, nullptr, HID, HID);
    }
    // x0 = relu(gcn2) into xjk cols [0,128)
    k_gcn_agg2<<<wblk(NTOT), GB>>>(p_A, b_m2, b_d2, p_xjk, p_xjk + (size_t)N_M * 224, 224, 224);

    // ---- GATv2 layer 1: xl|xr in ONE dual-W GEMM (K=128, Nc=256+256) ----
    {
        GTask ta = { p_xjk, Wl1, Wr1, p_A, p_B, NTOT };
        k_gemm<<<dim3(4, NTOT / 128, 1), 256>>>(ta, ta, 224, 256, 256, nullptr, 256, 128);
    }
    k_gat_fused<256><<<wblk(NTOT), GB>>>(p_A, p_B, att1, bias1, p_xjk + 128, 224, 1);

    // ---- GATv2 layer 2 (K=64, Nc=128+128) ----
    {
        GTask ta = { p_xjk + 128, Wl2, Wr2, p_A, p_B, NTOT };
        k_gemm<<<dim3(2, NTOT / 128, 1), 256>>>(ta, ta, 224, 128, 128, nullptr, 128, 64);
    }
    k_gat_fused<128><<<wblk(NTOT), GB>>>(p_A, p_B, att2, bias2, p_xjk + 192, 224, 0);

    // ---- JumpingKnowledge linear: out = [x0|x1|x2] @ Wjk + bjk ----
    {
        GTask ta = { p_xjk, Wjk, Wjk, out, out, NTOT };
        k_gemm<<<dim3(1, NTOT / 128, 1), 256>>>(ta, ta, 224, 128, 128, bjk, 128, 224);
    }
}

// round 9
// speedup vs baseline: 1.4748x; 1.4748x over previous
#include <cuda_runtime.h>
#include <math.h>
#include <stdint.h>

// ---------------- problem constants (fixed by the dataset) ----------------
#define N_M   8192
#define N_D   6144
#define NTOT  14336            // N_M + N_D
#define E_MM  131072
#define E_DD  98304
#define E_G   229376
#define EG_TOT (E_G + NTOT)    // real edges + self loops = 243712
#define HID   128
#define TPB   256

// ---------------- scratch (static device globals; no runtime alloc) -------
__device__ float g_ew_m[E_MM];
__device__ float g_ew_d[E_DD];
__device__ float g_deg_m[N_M];
__device__ float g_deg_d[N_D];
__device__ int   g_cnt_m[N_M],  g_row_m[N_M + 1],  g_cur_m[N_M];
__device__ int   g_src_m[E_MM];  __device__ float g_w_m[E_MM];
__device__ int   g_cnt_d[N_D],  g_row_d[N_D + 1],  g_cur_d[N_D];
__device__ int   g_src_d[E_DD];  __device__ float g_w_d[E_DD];
__device__ int   g_cnt_g[NTOT], g_row_g[NTOT + 1], g_cur_g[NTOT];
__device__ int   g_src_g[EG_TOT];
__device__ float g_bufA[(size_t)NTOT * 256];
__device__ float g_bufB[(size_t)NTOT * 256];
__device__ float g_tmp [(size_t)NTOT * 128];
__device__ float g_xjk [(size_t)NTOT * 224];

__device__ __forceinline__ float4 ld4(const float* p) { return *(const float4*)p; }

// tf32 conversion (round-to-nearest) — bit pattern in a u32
__device__ __forceinline__ uint32_t f2tf(float x) {
    uint32_t r;
    asm("cvt.rna.tf32.f32 %0, %1;" : "=r"(r) : "f"(x));
    return r;
}

// one m16n8k8 tf32 mma, D += A*B (D==C in-place)
__device__ __forceinline__ void mma8(float* d, const uint32_t* a, uint32_t b0, uint32_t b1) {
    asm("mma.sync.aligned.m16n8k8.row.col.f32.tf32.tf32.f32 "
        "{%0,%1,%2,%3}, {%4,%5,%6,%7}, {%8,%9}, {%0,%1,%2,%3};"
        : "+f"(d[0]), "+f"(d[1]), "+f"(d[2]), "+f"(d[3])
        : "r"(a[0]), "r"(a[1]), "r"(a[2]), "r"(a[3]), "r"(b0), "r"(b1));
}

// ---------------- init ----------------
__global__ void k_init() {
    int i = blockIdx.x * blockDim.x + threadIdx.x;
    if (i < N_M)  { g_deg_m[i] = 1.0f; g_cnt_m[i] = 0; }   // self-loop weight 1
    if (i < N_D)  { g_deg_d[i] = 1.0f; g_cnt_d[i] = 0; }
    if (i < NTOT) { g_cnt_g[i] = 1; }                       // self loop pre-counted
}

// ---------------- combined edge prep (both GCN graphs + GAT count) --------
__global__ void k_prep_all(const int* __restrict__ e_mm, const float* __restrict__ msM,
                           const int* __restrict__ e_dd, const float* __restrict__ dsM,
                           const int* __restrict__ e_g) {
    int i = blockIdx.x * blockDim.x + threadIdx.x;
    if (i < E_MM) {
        int s = e_mm[i], d = e_mm[E_MM + i];
        float w = msM[(size_t)s * N_M + d];
        g_ew_m[i] = w;
        atomicAdd(&g_deg_m[d], w);
        atomicAdd(&g_cnt_m[d], 1);
    } else if (i < E_MM + E_DD) {
        int f = i - E_MM;
        int s = e_dd[f], d = e_dd[E_DD + f];
        float w = dsM[(size_t)s * N_D + d];
        g_ew_d[f] = w;
        atomicAdd(&g_deg_d[d], w);
        atomicAdd(&g_cnt_d[d], 1);
    } else if (i < E_MM + E_DD + E_G) {
        int f = i - E_MM - E_DD;
        atomicAdd(&g_cnt_g[e_g[E_G + f]], 1);
    }
}

// ---------------- 3 scans in one launch (blockIdx picks the graph) --------
__global__ void k_scan3() {
    __shared__ int sh[1024];
    const int* cnt; int* row; int* cur; int n;
    if (blockIdx.x == 0)      { cnt = g_cnt_m; row = g_row_m; cur = g_cur_m; n = N_M; }
    else if (blockIdx.x == 1) { cnt = g_cnt_d; row = g_row_d; cur = g_cur_d; n = N_D; }
    else                      { cnt = g_cnt_g; row = g_row_g; cur = g_cur_g; n = NTOT; }
    int t = threadIdx.x;
    int chunk = (n + 1023) / 1024;
    int lo = t * chunk, hi = min(lo + chunk, n);
    int sum = 0;
    for (int i = lo; i < hi; i++) sum += cnt[i];
    sh[t] = sum;
    __syncthreads();
    for (int off = 1; off < 1024; off <<= 1) {
        int v = 0;
        if (t >= off) v = sh[t - off];
        __syncthreads();
        if (t >= off) sh[t] += v;
        __syncthreads();
    }
    int run = (t == 0) ? 0 : sh[t - 1];
    for (int i = lo; i < hi; i++) { row[i] = run; cur[i] = run; run += cnt[i]; }
    if (t == 1023) row[n] = sh[1023];
}

// ---------------- combined CSR fill; GCN norm computed inline -------------
__global__ void k_fill_all(const int* __restrict__ e_mm, const int* __restrict__ e_dd,
                           const int* __restrict__ e_g) {
    int i = blockIdx.x * blockDim.x + threadIdx.x;
    if (i < E_MM) {
        int s = e_mm[i], d = e_mm[E_MM + i];
        int p = atomicAdd(&g_cur_m[d], 1);
        g_src_m[p] = s;
        g_w_m[p] = rsqrtf(g_deg_m[s]) * g_ew_m[i] * rsqrtf(g_deg_m[d]);
    } else if (i < E_MM + E_DD) {
        int f = i - E_MM;
        int s = e_dd[f], d = e_dd[E_DD + f];
        int p = atomicAdd(&g_cur_d[d], 1);
        g_src_d[p] = s;
        g_w_d[p] = rsqrtf(g_deg_d[s]) * g_ew_d[f] * rsqrtf(g_deg_d[d]);
    } else if (i < E_MM + E_DD + E_G) {
        int f = i - E_MM - E_DD;
        int d = e_g[E_G + f];
        int p = atomicAdd(&g_cur_g[d], 1);
        g_src_g[p] = e_g[f];
    } else if (i < E_MM + E_DD + E_G + NTOT) {
        int f = i - E_MM - E_DD - E_G;     // self loop
        int p = atomicAdd(&g_cur_g[f], 1);
        g_src_g[p] = f;
    }
}

// ---------------- tf32x3 tensor-core GEMM: 128x64x16 tiles -----------------
// 8 warps (4m x 2n), warp tile m32 x n32, mma.m16n8k8.tf32, 3-pass comp.
// Smaller BN halves regs+smem vs 128x128 -> 3 blocks/SM, 2x block count:
// latency-bound before (occ 12%), so occupancy is the lever.
struct GTask { const float* A; const float* W1; const float* W2; float* C1; float* C2; int M; };

__global__ __launch_bounds__(256) void k_gemm(
        GTask ta, GTask tb,
        int lda, int Nsplit, int ldw, const float* bias, int ldc, int K) {
    __shared__ uint32_t As_h[16][132], As_l[16][132];   // [k][m], pad 4
    __shared__ uint32_t Bs_h[16][68],  Bs_l[16][68];    // [k][n], pad 4
    GTask t = (blockIdx.z == 0) ? ta : tb;
    int row0 = blockIdx.y * 128;
    if (row0 >= t.M) return;
    int col0 = blockIdx.x * 64;
    const float* Wb; float* Cb;
    if (col0 < Nsplit) { Wb = t.W1 + col0;            Cb = t.C1 + col0; }
    else               { Wb = t.W2 + (col0 - Nsplit); Cb = t.C2 + (col0 - Nsplit); }

    int tid = threadIdx.x;
    int lane = tid & 31, wid = tid >> 5;
    int warp_m = wid & 3, warp_n = wid >> 2;   // 4 x 2 warp grid
    int g = lane >> 2, tg = lane & 3;
    int mbase = warp_m * 32, nbase0 = warp_n * 32;

    float acc[2][4][4];
    #pragma unroll
    for (int mi = 0; mi < 2; mi++)
        #pragma unroll
        for (int ni = 0; ni < 4; ni++)
            #pragma unroll
            for (int q = 0; q < 4; q++) acc[mi][ni][q] = 0.f;

    for (int k0 = 0; k0 < K; k0 += 16) {
        // A tile 128x16 -> As[k][m] (transposed), split hi/lo; 2 float4/thread
        #pragma unroll
        for (int i = 0; i < 2; i++) {
            int idx = tid + i * 256;
            int r = idx >> 2, c4 = idx & 3;
            float4 v = ld4(t.A + (size_t)(row0 + r) * lda + k0 + c4 * 4);
            float e[4] = {v.x, v.y, v.z, v.w};
            #pragma unroll
            for (int j = 0; j < 4; j++) {
                uint32_t h = f2tf(e[j]);
                As_h[c4 * 4 + j][r] = h;
                As_l[c4 * 4 + j][r] = f2tf(e[j] - __uint_as_float(h));
            }
        }
        // B tile 16x64 -> Bs[k][n], split hi/lo; 1 float4/thread
        {
            int r = tid >> 4, c4 = tid & 15;
            float4 v = ld4(Wb + (size_t)(k0 + r) * ldw + c4 * 4);
            uint4 hv, lv;
            hv.x = f2tf(v.x); lv.x = f2tf(v.x - __uint_as_float(hv.x));
            hv.y = f2tf(v.y); lv.y = f2tf(v.y - __uint_as_float(hv.y));
            hv.z = f2tf(v.z); lv.z = f2tf(v.z - __uint_as_float(hv.z));
            hv.w = f2tf(v.w); lv.w = f2tf(v.w - __uint_as_float(hv.w));
            *(uint4*)&Bs_h[r][c4 * 4] = hv;
            *(uint4*)&Bs_l[r][c4 * 4] = lv;
        }
        __syncthreads();

        #pragma unroll
        for (int ks = 0; ks < 16; ks += 8) {
            uint32_t ah[2][4], al[2][4];
            #pragma unroll
            for (int mi = 0; mi < 2; mi++) {
                int m0 = mbase + mi * 16;
                ah[mi][0] = As_h[ks + tg][m0 + g];
                ah[mi][1] = As_h[ks + tg][m0 + g + 8];
                ah[mi][2] = As_h[ks + tg + 4][m0 + g];
                ah[mi][3] = As_h[ks + tg + 4][m0 + g + 8];
                al[mi][0] = As_l[ks + tg][m0 + g];
                al[mi][1] = As_l[ks + tg][m0 + g + 8];
                al[mi][2] = As_l[ks + tg + 4][m0 + g];
                al[mi][3] = As_l[ks + tg + 4][m0 + g + 8];
            }
            #pragma unroll
            for (int ni = 0; ni < 4; ni++) {
                int n0 = nbase0 + ni * 8;
                uint32_t bh0 = Bs_h[ks + tg][n0 + g];
                uint32_t bh1 = Bs_h[ks + tg + 4][n0 + g];
                uint32_t bl0 = Bs_l[ks + tg][n0 + g];
                uint32_t bl1 = Bs_l[ks + tg + 4][n0 + g];
                #pragma unroll
                for (int mi = 0; mi < 2; mi++) {
                    mma8(acc[mi][ni], ah[mi], bl0, bl1);   // hi * lo
                    mma8(acc[mi][ni], al[mi], bh0, bh1);   // lo * hi
                    mma8(acc[mi][ni], ah[mi], bh0, bh1);   // hi * hi
                }
            }
        }
        __syncthreads();
    }

    // epilogue: thread owns rows {g, g+8} of each m16 tile, cols {2tg, 2tg+1}
    #pragma unroll
    for (int mi = 0; mi < 2; mi++) {
        int r0 = row0 + mbase + mi * 16 + g;
        #pragma unroll
        for (int ni = 0; ni < 4; ni++) {
            int lc = nbase0 + ni * 8 + tg * 2;
            float b0 = 0.f, b1 = 0.f;
            if (bias) { b0 = bias[col0 + lc]; b1 = bias[col0 + lc + 1]; }
            float* p0 = Cb + (size_t)r0 * ldc + lc;
            float* p1 = p0 + (size_t)8 * ldc;
            *(float2*)p0 = make_float2(acc[mi][ni][0] + b0, acc[mi][ni][1] + b1);
            *(float2*)p1 = make_float2(acc[mi][ni][2] + b0, acc[mi][ni][3] + b1);
        }
    }
}

// ---------------- GCN aggregate, both graphs in one launch ----------------
__global__ void k_gcn_agg2(const float* __restrict__ h,
                           const float* __restrict__ bias_m, const float* __restrict__ bias_d,
                           float* __restrict__ out_m, float* __restrict__ out_d,
                           int ldm, int ldd) {
    int w = (blockIdx.x * blockDim.x + threadIdx.x) >> 5;
    int lane = threadIdx.x & 31;
    if (w >= NTOT) return;
    const int* row; const int* src; const float* wcs; const float* bias;
    const float* hb; const float* deg; float* po; int node;
    if (w < N_M) {
        node = w; row = g_row_m; src = g_src_m; wcs = g_w_m; bias = bias_m;
        hb = h; deg = g_deg_m;
        po = out_m + (size_t)w * ldm + lane * 4;
    } else {
        node = w - N_M; row = g_row_d; src = g_src_d; wcs = g_w_d; bias = bias_d;
        hb = h + (size_t)N_M * HID; deg = g_deg_d;
        po = out_d + (size_t)(w - N_M) * ldd + lane * 4;
    }
    int rs = row[node], re = row[node + 1];
    float4 acc = make_float4(0.f, 0.f, 0.f, 0.f);
    for (int j = rs; j < re; j++) {
        int s = src[j];
        float nm = wcs[j];
        float4 v = ld4(hb + (size_t)s * HID + lane * 4);
        acc.x += nm * v.x; acc.y += nm * v.y; acc.z += nm * v.z; acc.w += nm * v.w;
    }
    float di = rsqrtf(deg[node]);
    float sw = di * di;
    float4 v = ld4(hb + (size_t)node * HID + lane * 4);
    acc.x += sw * v.x; acc.y += sw * v.y; acc.z += sw * v.z; acc.w += sw * v.w;
    float4 b = ld4(bias + lane * 4);
    acc.x = fmaxf(acc.x + b.x, 0.f); acc.y = fmaxf(acc.y + b.y, 0.f);
    acc.z = fmaxf(acc.z + b.z, 0.f); acc.w = fmaxf(acc.w + b.w, 0.f);
    *(float4*)po = acc;
}

// ---------------- Fused GATv2 (warp per dst node, online softmax) ---------
template <int HC>
__global__ void k_gat_fused(const float* __restrict__ xl, const float* __restrict__ xr,
                            const float* __restrict__ att,
                            const float* __restrict__ bias,
                            float* __restrict__ out, int ldout, int elu) {
    const int CH = HC / 32;
    int i = (blockIdx.x * blockDim.x + threadIdx.x) >> 5;
    int lane = threadIdx.x & 31;
    if (i >= NTOT) return;
    int rs = g_row_g[i], re = g_row_g[i + 1];

    float attv[CH], xrv[CH];
    #pragma unroll
    for (int k = 0; k < CH; k += 4) {
        float4 a = ld4(att + lane * CH + k);
        attv[k] = a.x; attv[k + 1] = a.y; attv[k + 2] = a.z; attv[k + 3] = a.w;
        float4 r = ld4(xr + (size_t)i * HC + lane * CH + k);
        xrv[k] = r.x; xrv[k + 1] = r.y; xrv[k + 2] = r.z; xrv[k + 3] = r.w;
    }

    float m = -1e30f, den = 0.f;
    float num[CH];
    #pragma unroll
    for (int k = 0; k < CH; k++) num[k] = 0.f;

    for (int j = rs; j < re; j++) {
        int s = g_src_g[j];
        float xlv[CH];
        float p = 0.f;
        #pragma unroll
        for (int k = 0; k < CH; k += 4) {
            float4 v = ld4(xl + (size_t)s * HC + lane * CH + k);
            xlv[k] = v.x; xlv[k + 1] = v.y; xlv[k + 2] = v.z; xlv[k + 3] = v.w;
        }
        #pragma unroll
        for (int k = 0; k < CH; k++) {
            float t = xlv[k] + xrv[k];
            t = t > 0.f ? t : 0.2f * t;
            p += t * attv[k];
        }
        p += __shfl_xor_sync(0xffffffffu, p, 1);
        p += __shfl_xor_sync(0xffffffffu, p, 2);
        p += __shfl_xor_sync(0xffffffffu, p, 4);
        float mn = fmaxf(m, p);
        float c  = expf(m - mn);      // first iter: exp(-huge) = 0
        float ex = expf(p - mn);
        den = den * c + ex;
        #pragma unroll
        for (int k = 0; k < CH; k++) num[k] = num[k] * c + ex * xlv[k];
        m = mn;
    }

    float inv = 0.25f / den;   // includes 1/H head-mean
    #pragma unroll
    for (int k = 0; k < CH; k++) {
        float v = num[k] * inv;
        v += __shfl_xor_sync(0xffffffffu, v, 8);
        v += __shfl_xor_sync(0xffffffffu, v, 16);
        num[k] = v;
    }
    if (lane < 8) {
        float o[CH];
        #pragma unroll
        for (int k = 0; k < CH; k++) {
            float v = num[k] + bias[lane * CH + k];
            if (elu) v = v > 0.f ? v : expm1f(v);
            o[k] = v;
        }
        float* po = out + (size_t)i * ldout + lane * CH;
        #pragma unroll
        for (int k = 0; k < CH; k += 4)
            *(float4*)(po + k) = make_float4(o[k], o[k + 1], o[k + 2], o[k + 3]);
    }
}

// ---------------- host orchestration ----------------
extern "C" void kernel_launch(void* const* d_in, const int* in_sizes, int n_in,
                              void* d_out, int out_size) {
    const float* mm_f = (const float*)d_in[0];
    const float* d_s  = (const float*)d_in[1];
    const float* msM  = (const float*)d_in[2];
    const float* dsM  = (const float*)d_in[3];
    const int*   e_mm = (const int*)d_in[4];
    const int*   e_dd = (const int*)d_in[5];
    const int*   e_g  = (const int*)d_in[6];
    const float* W_m1 = (const float*)d_in[7];  const float* b_m1 = (const float*)d_in[8];
    const float* W_m2 = (const float*)d_in[9];  const float* b_m2 = (const float*)d_in[10];
    const float* W_d1 = (const float*)d_in[11]; const float* b_d1 = (const float*)d_in[12];
    const float* W_d2 = (const float*)d_in[13]; const float* b_d2 = (const float*)d_in[14];
    const float* Wl1  = (const float*)d_in[15]; const float* Wr1  = (const float*)d_in[16];
    const float* att1 = (const float*)d_in[17]; const float* bias1 = (const float*)d_in[18];
    const float* Wl2  = (const float*)d_in[19]; const float* Wr2  = (const float*)d_in[20];
    const float* att2 = (const float*)d_in[21]; const float* bias2 = (const float*)d_in[22];
    const float* Wjk  = (const float*)d_in[23]; const float* bjk  = (const float*)d_in[24];
    float* out = (float*)d_out;

    float *p_A, *p_B, *p_tmp, *p_xjk;
    cudaGetSymbolAddress((void**)&p_A,   g_bufA);
    cudaGetSymbolAddress((void**)&p_B,   g_bufB);
    cudaGetSymbolAddress((void**)&p_tmp, g_tmp);
    cudaGetSymbolAddress((void**)&p_xjk, g_xjk);

    const int GB = TPB;
    auto blk = [](int n) { return (n + TPB - 1) / TPB; };
    auto wblk = [](int nwarps) { return (nwarps * 32 + TPB - 1) / TPB; };

    // ---- prep + GCN layer1 GEMM (gemm at ncu slot #4) ----
    k_init<<<blk(NTOT), GB>>>();
    k_prep_all<<<blk(E_MM + E_DD + E_G), GB>>>(e_mm, msM, e_dd, dsM, e_g);
    k_scan3<<<3, 1024>>>();
    {
        GTask ta = { mm_f, W_m1, W_m1, p_A,                      p_A,                      N_M };
        GTask tb = { d_s,  W_d1, W_d1, p_A + (size_t)N_M * HID,  p_A + (size_t)N_M * HID,  N_D };
        k_gemm<<<dim3(2, N_M / 128, 2), 256>>>(ta, tb, HID, 128, HID, nullptr, HID, HID);
    }
    k_fill_all<<<blk(E_MM + E_DD + E_G + NTOT), GB>>>(e_mm, e_dd, e_g);

    // ---- GCN layer 1 aggregate ----
    k_gcn_agg2<<<wblk(NTOT), GB>>>(p_A, b_m1, b_d1, p_tmp, p_tmp + (size_t)N_M * HID, HID, HID);

    // ---- GCN layer 2 ----
    {
        GTask ta = { p_tmp,                      W_m2, W_m2, p_A,                     p_A,                     N_M };
        GTask tb = { p_tmp + (size_t)N_M * HID,  W_d2, W_d2, p_A + (size_t)N_M * HID, p_A + (size_t)N_M * HID, N_D };
        k_gemm<<<dim3(2, N_M / 128, 2), 256>>>(ta, tb, HID, 128, HID, nullptr, HID, HID);
    }
    // x0 = relu(gcn2) into xjk cols [0,128)
    k_gcn_agg2<<<wblk(NTOT), GB>>>(p_A, b_m2, b_d2, p_xjk, p_xjk + (size_t)N_M * 224, 224, 224);

    // ---- GATv2 layer 1: xl|xr in ONE dual-W GEMM (K=128, Nc=256+256) ----
    {
        GTask ta = { p_xjk, Wl1, Wr1, p_A, p_B, NTOT };
        k_gemm<<<dim3(8, NTOT / 128, 1), 256>>>(ta, ta, 224, 256, 256, nullptr, 256, 128);
    }
    k_gat_fused<256><<<wblk(NTOT), GB>>>(p_A, p_B, att1, bias1, p_xjk + 128, 224, 1);

    // ---- GATv2 layer 2 (K=64, Nc=128+128) ----
    {
        GTask ta = { p_xjk + 128, Wl2, Wr2, p_A, p_B, NTOT };
        k_gemm<<<dim3(4, NTOT / 128, 1), 256>>>(ta, ta, 224, 128, 128, nullptr, 128, 64);
    }
    k_gat_fused<128><<<wblk(NTOT), GB>>>(p_A, p_B, att2, bias2, p_xjk + 192, 224, 0);

    // ---- JumpingKnowledge linear: out = [x0|x1|x2] @ Wjk + bjk ----
    {
        GTask ta = { p_xjk, Wjk, Wjk, out, out, NTOT };
        k_gemm<<<dim3(2, NTOT / 128, 1), 256>>>(ta, ta, 224, 128, 128, bjk, 128, 224);
    }
}